// round 10
// baseline (speedup 1.0000x reference)
#include <cuda_runtime.h>
#include <cuda_fp16.h>
#include <cstdint>

// TDNN as implicit GEMM, single-pass fp16 mma.sync (HMMA).
//   out[b,n,t] = relu(bias[n] + sum_{kappa<2560} W2[n][kappa] * x[b, t*512+kappa])
// Round 10: barrier relocated to kk=3 (tensor queue full when it executes),
// cross-stage fragment prefetch so the first HMMA after the barrier has its
// operands in registers. One wait_group + one __syncthreads per stage.

#define DIN   512
#define DOUT  512
#define TIN   1024
#define TOUT  1020
#define KW    5
#define KTOT  2560
#define BATCH 32

#define TILE_M 128
#define TILE_N 128
#define KC     64
#define NSTAGE (KTOT / KC)

#define XVEC_BLOCKS ((BATCH * TIN * DIN) / 8 / 256)   // 8192
#define WPAIR_BLOCKS ((DOUT * DIN) / 256)             // 1024

// ---------------- scratch (no allocation allowed) ----------------
__device__ __half g_xh[(size_t)BATCH * TIN * DIN];
__device__ __half g_wh[DOUT * KTOT];   // [n][k*512+i]

__global__ void split_inputs(const float* __restrict__ x,
                             const float* __restrict__ w) {
    int bid = blockIdx.x;
    if (bid < XVEC_BLOCKS) {
        int i8 = (bid * 256 + threadIdx.x) * 8;
        float4 v0 = *(const float4*)(x + i8);
        float4 v1 = *(const float4*)(x + i8 + 4);
        __half2 h0 = __floats2half2_rn(v0.x, v0.y);
        __half2 h1 = __floats2half2_rn(v0.z, v0.w);
        __half2 h2 = __floats2half2_rn(v1.x, v1.y);
        __half2 h3 = __floats2half2_rn(v1.z, v1.w);
        uint4 pk;
        pk.x = *(uint32_t*)&h0;
        pk.y = *(uint32_t*)&h1;
        pk.z = *(uint32_t*)&h2;
        pk.w = *(uint32_t*)&h3;
        *(uint4*)(g_xh + i8) = pk;
    } else {
        int p = (bid - XVEC_BLOCKS) * 256 + threadIdx.x;   // p = n*512 + i
        int n = p >> 9;
        int i = p & 511;
        const float* wp = w + (size_t)p * KW;
        #pragma unroll
        for (int k = 0; k < KW; ++k)
            g_wh[n * KTOT + k * DIN + i] = __float2half_rn(wp[k]);
    }
}

// ---------------- PTX helpers (portable) ----------------
__device__ __forceinline__ uint32_t smem_u32(const void* p) {
    uint32_t a;
    asm("{ .reg .u64 t; cvta.to.shared.u64 t, %1; cvt.u32.u64 %0, t; }"
        : "=r"(a) : "l"(p));
    return a;
}
__device__ __forceinline__ void cpa16(uint32_t dst, const void* src) {
    asm volatile("cp.async.cg.shared.global [%0], [%1], 16;"
                 :: "r"(dst), "l"(__cvta_generic_to_global(src)) : "memory");
}
__device__ __forceinline__ void ldsm4(uint32_t* r, uint32_t a) {
    asm volatile("ldmatrix.sync.aligned.m8n8.x4.shared.b16 {%0,%1,%2,%3}, [%4];"
                 : "=r"(r[0]), "=r"(r[1]), "=r"(r[2]), "=r"(r[3]) : "r"(a));
}
__device__ __forceinline__ void mma16816(float* c, const uint32_t* a,
                                         const uint32_t* b) {
    asm volatile(
        "mma.sync.aligned.m16n8k16.row.col.f32.f16.f16.f32 "
        "{%0,%1,%2,%3}, {%4,%5,%6,%7}, {%8,%9}, {%0,%1,%2,%3};"
        : "+f"(c[0]), "+f"(c[1]), "+f"(c[2]), "+f"(c[3])
        : "r"(a[0]), "r"(a[1]), "r"(a[2]), "r"(a[3]), "r"(b[0]), "r"(b[1]));
}
#define WAITG1() asm volatile("cp.async.wait_group 1;" ::: "memory")
#define WAITG0() asm volatile("cp.async.wait_group 0;" ::: "memory")
#define WAITG2() asm volatile("cp.async.wait_group 2;" ::: "memory")

#define A_OFF 0u
#define B_OFF 16384u
#define STAGE_BYTES 32768u
#define NBUF 3
#define SMEM_BYTES (1024 + NBUF * 32768)

extern __shared__ char dyn_smem[];

__global__ __launch_bounds__(256, 2)
void tdnn_mma(const float* __restrict__ bias, float* __restrict__ out) {
    const int tid  = threadIdx.x;
    const int wid  = tid >> 5;
    const int lane = tid & 31;
    const int d0 = blockIdx.x * TILE_M;
    const int t0 = blockIdx.y * TILE_N;
    const int b  = blockIdx.z;

    const int wm = wid & 1;   // 2 warps along M (64 rows each)
    const int wn = wid >> 1;  // 4 warps along N (32 cols each)

    const uint32_t sb = (smem_u32(dyn_smem) + 1023u) & ~1023u;
    const int rmax = (TIN - KW) - t0;

    // ---- per-lane ldmatrix address precompute (SW128: 128B rows) ----
    const int grp  = lane >> 3;
    const int apar = grp >> 1;
    uint32_t a_off[4]; int a_sw[4];
    #pragma unroll
    for (int mt = 0; mt < 4; ++mt) {
        int r = wm * 64 + mt * 16 + ((grp & 1) << 3) + (lane & 7);
        a_off[mt] = (uint32_t)(r << 7);
        a_sw[mt]  = r & 7;
    }
    const int bpar  = grp & 1;
    const int ntoff = grp >> 1;
    uint32_t b_off[2]; int b_sw[2];
    #pragma unroll
    for (int np = 0; np < 2; ++np) {
        int r = wn * 32 + np * 16 + ntoff * 8 + (lane & 7);
        b_off[np] = (uint32_t)(r << 7);
        b_sw[np]  = r & 7;
    }

    float acc[4][4][4];
    #pragma unroll
    for (int mt = 0; mt < 4; ++mt)
        #pragma unroll
        for (int nt = 0; nt < 4; ++nt)
            #pragma unroll
            for (int q = 0; q < 4; ++q) acc[mt][nt][q] = 0.0f;

    auto load_stage = [&](int s, uint32_t base) {
        const int kc = s * KC;
        #pragma unroll 4
        for (int c = tid; c < 1024; c += 256) {      // A
            int row = c >> 3, ch = c & 7;
            uint32_t off = (uint32_t)((row << 7) | ((ch ^ (row & 7)) << 4));
            size_t gi = (size_t)(d0 + row) * KTOT + kc + ch * 8;
            cpa16(base + A_OFF + off, g_wh + gi);
        }
        #pragma unroll 4
        for (int c = tid; c < 1024; c += 256) {      // B
            int row = c >> 3, ch = c & 7;
            int t = t0 + min(row, rmax);
            uint32_t off = (uint32_t)((row << 7) | ((ch ^ (row & 7)) << 4));
            size_t gi = (size_t)b * (TIN * DIN) + (size_t)t * DIN + kc + ch * 8;
            cpa16(base + B_OFF + off, g_xh + gi);
        }
        asm volatile("cp.async.commit_group;" ::: "memory");
    };

    // fragment load for (buffer base, kk)
    uint32_t afr[2][4][4], bfr[2][8];
    auto ld_frags = [&](int slot, uint32_t base, int kk) {
        #pragma unroll
        for (int mt = 0; mt < 4; ++mt) {
            uint32_t co = (uint32_t)((((kk << 1) + apar) ^ a_sw[mt]) << 4);
            ldsm4(afr[slot][mt], base + A_OFF + a_off[mt] + co);
        }
        #pragma unroll
        for (int np = 0; np < 2; ++np) {
            uint32_t co = (uint32_t)((((kk << 1) + bpar) ^ b_sw[np]) << 4);
            ldsm4(&bfr[slot][np * 4], base + B_OFF + b_off[np] + co);
        }
    };
    auto mma_all = [&](int slot) {
        #pragma unroll
        for (int mt = 0; mt < 4; ++mt)
            #pragma unroll
            for (int nt = 0; nt < 4; ++nt)
                mma16816(acc[mt][nt], afr[slot][mt], &bfr[slot][nt * 2]);
    };

    // ---- prologue ----
    load_stage(0, sb);
    load_stage(1, sb + STAGE_BYTES);
    load_stage(2, sb + 2 * STAGE_BYTES);
    WAITG2();                 // group 0 landed
    __syncthreads();
    ld_frags(0, sb, 0);       // kk0 of stage 0

    int cur = 0;
    for (int s = 0; s < NSTAGE; ++s) {
        const uint32_t bs = sb + (uint32_t)(s % 3) * STAGE_BYTES;
        // kk = 0..2: compute current, prefetch next kk
        #pragma unroll
        for (int kk = 0; kk < 3; ++kk) {
            ld_frags(cur ^ 1, bs, kk + 1);
            mma_all(cur);
            cur ^= 1;
        }
        // kk = 3: barrier while tensor queue is full, then cross-stage work
        if (s < NSTAGE - 2) { WAITG1(); }     // group s+1 landed
        else                { WAITG0(); }
        __syncthreads();
        // overwrite this stage's buffer (all ldsm reads of it done pre-barrier)
        if (s + 3 < NSTAGE) load_stage(s + 3, bs);
        // prefetch kk0 of next stage (its group just waited on)
        if (s + 1 < NSTAGE)
            ld_frags(cur ^ 1, sb + (uint32_t)((s + 1) % 3) * STAGE_BYTES, 0);
        mma_all(cur);         // kk3 (fragments loaded during kk2)
        cur ^= 1;
    }

    // ---- epilogue: bias + relu; float2 stores ----
    const int quad = lane >> 2;
    const int qt   = (lane & 3) << 1;
    #pragma unroll
    for (int mt = 0; mt < 4; ++mt) {
        const int m = d0 + wm * 64 + mt * 16 + quad;
        const float bv0 = bias[m];
        const float bv1 = bias[m + 8];
        float* r0 = out + ((size_t)b * DOUT + m) * TOUT;
        float* r1 = r0 + 8 * TOUT;
        #pragma unroll
        for (int nt = 0; nt < 4; ++nt) {
            const int t = t0 + wn * 32 + nt * 8 + qt;
            if (t < TOUT) {
                float2 v0, v1;
                v0.x = fmaxf(acc[mt][nt][0] + bv0, 0.0f);
                v0.y = fmaxf(acc[mt][nt][1] + bv0, 0.0f);
                v1.x = fmaxf(acc[mt][nt][2] + bv1, 0.0f);
                v1.y = fmaxf(acc[mt][nt][3] + bv1, 0.0f);
                *(float2*)&r0[t] = v0;
                *(float2*)&r1[t] = v1;
            }
        }
    }
}

extern "C" void kernel_launch(void* const* d_in, const int* in_sizes, int n_in,
                              void* d_out, int out_size) {
    const float* x    = (const float*)d_in[0];
    const float* w    = (const float*)d_in[1];
    const float* bias = (const float*)d_in[2];
    float* out = (float*)d_out;

    cudaFuncSetAttribute(tdnn_mma, cudaFuncAttributeMaxDynamicSharedMemorySize,
                         SMEM_BYTES);

    split_inputs<<<XVEC_BLOCKS + WPAIR_BLOCKS, 256>>>(x, w);

    dim3 grid(DOUT / TILE_M, (TOUT + TILE_N - 1) / TILE_N, BATCH);  // (4,8,32)
    tdnn_mma<<<grid, 256, SMEM_BYTES>>>(bias, out);
}

// round 11
// speedup vs baseline: 1.0854x; 1.0854x over previous
#include <cuda_runtime.h>
#include <cuda_fp16.h>
#include <cstdint>

// TDNN as implicit GEMM, single-pass fp16 mma.sync (HMMA).
//   out[b,n,t] = relu(bias[n] + sum_{k<5,i<512} w[n][i][k] * x[b][t+k][i])
// Round 11: K reordered to (i-block outer, tap inner). One B tile of 136 rows
// of x per 64-channel i-block serves all 5 taps (ldsm row offset = k),
// cutting B cp.async traffic 4.85x. Compute loop identical to the best (R6).

#define DIN   512
#define DOUT  512
#define TIN   1024
#define TOUT  1020
#define KW    5
#define KTOT  2560
#define BATCH 32

#define TILE_M 128
#define TILE_N 128
#define NIB    8            // i-blocks of 64 channels
#define NSTAGE 40           // 8 i-blocks x 5 taps

#define XVEC_BLOCKS ((BATCH * TIN * DIN) / 8 / 256)   // 8192
#define WPAIR_BLOCKS ((DOUT * DIN) / 256)             // 1024

// ---------------- scratch (no allocation allowed) ----------------
__device__ __half g_xh[(size_t)BATCH * TIN * DIN];
__device__ __half g_wh[DOUT * KTOT];   // [n][k*512+i]

__global__ void split_inputs(const float* __restrict__ x,
                             const float* __restrict__ w) {
    int bid = blockIdx.x;
    if (bid < XVEC_BLOCKS) {
        int i8 = (bid * 256 + threadIdx.x) * 8;
        float4 v0 = *(const float4*)(x + i8);
        float4 v1 = *(const float4*)(x + i8 + 4);
        __half2 h0 = __floats2half2_rn(v0.x, v0.y);
        __half2 h1 = __floats2half2_rn(v0.z, v0.w);
        __half2 h2 = __floats2half2_rn(v1.x, v1.y);
        __half2 h3 = __floats2half2_rn(v1.z, v1.w);
        uint4 pk;
        pk.x = *(uint32_t*)&h0;
        pk.y = *(uint32_t*)&h1;
        pk.z = *(uint32_t*)&h2;
        pk.w = *(uint32_t*)&h3;
        *(uint4*)(g_xh + i8) = pk;
    } else {
        int p = (bid - XVEC_BLOCKS) * 256 + threadIdx.x;   // p = n*512 + i
        int n = p >> 9;
        int i = p & 511;
        const float* wp = w + (size_t)p * KW;
        #pragma unroll
        for (int k = 0; k < KW; ++k)
            g_wh[n * KTOT + k * DIN + i] = __float2half_rn(wp[k]);
    }
}

// ---------------- PTX helpers (portable) ----------------
__device__ __forceinline__ uint32_t smem_u32(const void* p) {
    uint32_t a;
    asm("{ .reg .u64 t; cvta.to.shared.u64 t, %1; cvt.u32.u64 %0, t; }"
        : "=r"(a) : "l"(p));
    return a;
}
__device__ __forceinline__ void cpa16(uint32_t dst, const void* src) {
    asm volatile("cp.async.cg.shared.global [%0], [%1], 16;"
                 :: "r"(dst), "l"(__cvta_generic_to_global(src)) : "memory");
}
__device__ __forceinline__ void ldsm4(uint32_t* r, uint32_t a) {
    asm volatile("ldmatrix.sync.aligned.m8n8.x4.shared.b16 {%0,%1,%2,%3}, [%4];"
                 : "=r"(r[0]), "=r"(r[1]), "=r"(r[2]), "=r"(r[3]) : "r"(a));
}
__device__ __forceinline__ void mma16816(float* c, const uint32_t* a,
                                         const uint32_t* b) {
    asm volatile(
        "mma.sync.aligned.m16n8k16.row.col.f32.f16.f16.f32 "
        "{%0,%1,%2,%3}, {%4,%5,%6,%7}, {%8,%9}, {%0,%1,%2,%3};"
        : "+f"(c[0]), "+f"(c[1]), "+f"(c[2]), "+f"(c[3])
        : "r"(a[0]), "r"(a[1]), "r"(a[2]), "r"(a[3]), "r"(b[0]), "r"(b[1]));
}

// SMEM: A 3 x 16KB @ 0, B 2 x 17408B (136 rows x 128B) @ 49152
#define A_STAGE 16384u
#define B_BASE  49152u
#define B_STAGE 17408u
#define B_ROWS  136
#define SMEM_BYTES (1024 + 49152 + 2 * 17408)

extern __shared__ char dyn_smem[];

__global__ __launch_bounds__(256, 2)
void tdnn_mma(const float* __restrict__ bias, float* __restrict__ out) {
    const int tid  = threadIdx.x;
    const int wid  = tid >> 5;
    const int lane = tid & 31;
    const int d0 = blockIdx.x * TILE_M;
    const int t0 = blockIdx.y * TILE_N;
    const int b  = blockIdx.z;

    const int wm = wid & 1;   // 2 warps along M (64 rows each)
    const int wn = wid >> 1;  // 4 warps along N (32 cols each)

    const uint32_t sb = (smem_u32(dyn_smem) + 1023u) & ~1023u;

    // ---- per-lane ldmatrix address precompute (SW128: 128B rows) ----
    const int grp  = lane >> 3;
    const int apar = grp >> 1;
    uint32_t a_off[4]; int a_sw[4];
    #pragma unroll
    for (int mt = 0; mt < 4; ++mt) {
        int r = wm * 64 + mt * 16 + ((grp & 1) << 3) + (lane & 7);
        a_off[mt] = (uint32_t)(r << 7);
        a_sw[mt]  = r & 7;
    }
    const int bpar  = grp & 1;
    const int ntoff = grp >> 1;
    int rbB[2];
    #pragma unroll
    for (int np = 0; np < 2; ++np)
        rbB[np] = wn * 32 + np * 16 + ntoff * 8 + (lane & 7);

    float acc[4][4][4];
    #pragma unroll
    for (int mt = 0; mt < 4; ++mt)
        #pragma unroll
        for (int nt = 0; nt < 4; ++nt)
            #pragma unroll
            for (int q = 0; q < 4; ++q) acc[mt][nt][q] = 0.0f;

    // B tile loader for i-block ib: 136 rows x 64 ch of x (all 5 tap shifts).
    auto load_B = [&](int ib) {
        const uint32_t bbase = sb + B_BASE + (uint32_t)(ib & 1) * B_STAGE;
        const int col0 = ib * 64;
        #pragma unroll 5
        for (int c = tid; c < B_ROWS * 8; c += 256) {
            int row = c >> 3, ch = c & 7;
            int t = min(t0 + row, TIN - 1);     // clamped rows feed only masked outputs
            uint32_t off = (uint32_t)((row << 7) | ((ch ^ (row & 7)) << 4));
            size_t gi = (size_t)b * (TIN * DIN) + (size_t)t * DIN + col0 + ch * 8;
            cpa16(bbase + off, g_xh + gi);
        }
    };

    // A loader for stage s = ib*5 + k. At k==3, also loads B(ib+1) (same group).
    auto load_stage = [&](int s) {
        const int ib = s / 5;
        const int k  = s - ib * 5;
        const uint32_t abase = sb + (uint32_t)(s % 3) * A_STAGE;
        const int kc = k * 512 + ib * 64;
        #pragma unroll 4
        for (int c = tid; c < 1024; c += 256) {
            int row = c >> 3, ch = c & 7;
            uint32_t off = (uint32_t)((row << 7) | ((ch ^ (row & 7)) << 4));
            size_t gi = (size_t)(d0 + row) * KTOT + kc + ch * 8;
            cpa16(abase + off, g_wh + gi);
        }
        if (k == 3 && ib < NIB - 1) load_B(ib + 1);
        asm volatile("cp.async.commit_group;" ::: "memory");
    };

    // ---- prologue: B(0) + A(0) as group 0; A(1) as group 1 ----
    load_B(0);
    load_stage(0);
    load_stage(1);

    for (int s = 0; s < NSTAGE; ++s) {
        if (s < NSTAGE - 1) asm volatile("cp.async.wait_group 1;" ::: "memory");
        else                asm volatile("cp.async.wait_group 0;" ::: "memory");
        __syncthreads();
        // A buffer (s+2)%3 == (s-1)%3: drained before this barrier.
        // B(ib'+1) inside group s+2 targets the buffer last read at stage
        // ib'*5-1 <= s, also drained.
        if (s + 2 < NSTAGE) load_stage(s + 2);

        const int ib = s / 5;
        const int k  = s - ib * 5;
        const uint32_t abase = sb + (uint32_t)(s % 3) * A_STAGE;
        const uint32_t bbase = sb + B_BASE + (uint32_t)(ib & 1) * B_STAGE;
        #pragma unroll
        for (int kk = 0; kk < 4; ++kk) {
            uint32_t af[4][4], bf[8];
            #pragma unroll
            for (int mt = 0; mt < 4; ++mt) {
                uint32_t co = (uint32_t)((((kk << 1) + apar) ^ a_sw[mt]) << 4);
                ldsm4(af[mt], abase + a_off[mt] + co);
            }
            #pragma unroll
            for (int np = 0; np < 2; ++np) {
                int r = rbB[np] + k;    // tap shift in rows
                uint32_t off = (uint32_t)((r << 7) |
                               ((((kk << 1) + bpar) ^ (r & 7)) << 4));
                ldsm4(&bf[np * 4], bbase + off);
            }
            #pragma unroll
            for (int mt = 0; mt < 4; ++mt)
                #pragma unroll
                for (int nt = 0; nt < 4; ++nt)
                    mma16816(acc[mt][nt], af[mt], &bf[nt * 2]);
        }
    }

    // ---- epilogue: bias + relu; float2 stores ----
    const int quad = lane >> 2;
    const int qt   = (lane & 3) << 1;
    #pragma unroll
    for (int mt = 0; mt < 4; ++mt) {
        const int m = d0 + wm * 64 + mt * 16 + quad;
        const float bv0 = bias[m];
        const float bv1 = bias[m + 8];
        float* r0 = out + ((size_t)b * DOUT + m) * TOUT;
        float* r1 = r0 + 8 * TOUT;
        #pragma unroll
        for (int nt = 0; nt < 4; ++nt) {
            const int t = t0 + wn * 32 + nt * 8 + qt;
            if (t < TOUT) {
                float2 v0, v1;
                v0.x = fmaxf(acc[mt][nt][0] + bv0, 0.0f);
                v0.y = fmaxf(acc[mt][nt][1] + bv0, 0.0f);
                v1.x = fmaxf(acc[mt][nt][2] + bv1, 0.0f);
                v1.y = fmaxf(acc[mt][nt][3] + bv1, 0.0f);
                *(float2*)&r0[t] = v0;
                *(float2*)&r1[t] = v1;
            }
        }
    }
}

extern "C" void kernel_launch(void* const* d_in, const int* in_sizes, int n_in,
                              void* d_out, int out_size) {
    const float* x    = (const float*)d_in[0];
    const float* w    = (const float*)d_in[1];
    const float* bias = (const float*)d_in[2];
    float* out = (float*)d_out;

    cudaFuncSetAttribute(tdnn_mma, cudaFuncAttributeMaxDynamicSharedMemorySize,
                         SMEM_BYTES);

    split_inputs<<<XVEC_BLOCKS + WPAIR_BLOCKS, 256>>>(x, w);

    dim3 grid(DOUT / TILE_M, (TOUT + TILE_N - 1) / TILE_N, BATCH);  // (4,8,32)
    tdnn_mma<<<grid, 256, SMEM_BYTES>>>(bias, out);
}

// round 12
// speedup vs baseline: 1.1589x; 1.0677x over previous
#include <cuda_runtime.h>
#include <cuda_fp16.h>
#include <cstdint>

// TDNN as implicit GEMM, single-pass fp16 mma.sync (HMMA).
//   out[b,n,t] = relu(bias[n] + sum_{kappa<2560} W2[n][kappa] * x[b, t*512+kappa])
// Round 12: main kernel reverted verbatim to the measured-best R6 structure
// (smem-port/tensor co-bound at ~73% duty -- roofline for mma.sync here).
// Split kernel rewritten for higher MLP: 16 x-elems/thread, 4 independent
// float4 loads -> ~12-14us (was ~16.4us).

#define DIN   512
#define DOUT  512
#define TIN   1024
#define TOUT  1020
#define KW    5
#define KTOT  2560
#define BATCH 32

#define TILE_M 128
#define TILE_N 128
#define KC     64
#define NSTAGE (KTOT / KC)

#define XVEC_BLOCKS ((BATCH * TIN * DIN) / 16 / 256)  // 4096
#define WPAIR_BLOCKS ((DOUT * DIN) / 256)             // 1024

// ---------------- scratch (no allocation allowed) ----------------
__device__ __half g_xh[(size_t)BATCH * TIN * DIN];
__device__ __half g_wh[DOUT * KTOT];   // [n][k*512+i]

__global__ void split_inputs(const float* __restrict__ x,
                             const float* __restrict__ w) {
    int bid = blockIdx.x;
    if (bid < XVEC_BLOCKS) {
        // 16 elems per thread: 4 independent float4 loads (MLP=4)
        int i16 = (bid * 256 + threadIdx.x) * 16;
        float4 v0 = *(const float4*)(x + i16);
        float4 v1 = *(const float4*)(x + i16 + 4);
        float4 v2 = *(const float4*)(x + i16 + 8);
        float4 v3 = *(const float4*)(x + i16 + 12);
        __half2 h0 = __floats2half2_rn(v0.x, v0.y);
        __half2 h1 = __floats2half2_rn(v0.z, v0.w);
        __half2 h2 = __floats2half2_rn(v1.x, v1.y);
        __half2 h3 = __floats2half2_rn(v1.z, v1.w);
        __half2 h4 = __floats2half2_rn(v2.x, v2.y);
        __half2 h5 = __floats2half2_rn(v2.z, v2.w);
        __half2 h6 = __floats2half2_rn(v3.x, v3.y);
        __half2 h7 = __floats2half2_rn(v3.z, v3.w);
        uint4 p0, p1;
        p0.x = *(uint32_t*)&h0;
        p0.y = *(uint32_t*)&h1;
        p0.z = *(uint32_t*)&h2;
        p0.w = *(uint32_t*)&h3;
        p1.x = *(uint32_t*)&h4;
        p1.y = *(uint32_t*)&h5;
        p1.z = *(uint32_t*)&h6;
        p1.w = *(uint32_t*)&h7;
        *(uint4*)(g_xh + i16)     = p0;
        *(uint4*)(g_xh + i16 + 8) = p1;
    } else {
        // one thread per (n,i): 5 contiguous fp32 reads, 5 coalesced fp16 writes
        int p = (bid - XVEC_BLOCKS) * 256 + threadIdx.x;   // p = n*512 + i
        int n = p >> 9;
        int i = p & 511;
        const float* wp = w + (size_t)p * KW;
        #pragma unroll
        for (int k = 0; k < KW; ++k)
            g_wh[n * KTOT + k * DIN + i] = __float2half_rn(wp[k]);
    }
}

// ---------------- PTX helpers (portable) ----------------
__device__ __forceinline__ uint32_t smem_u32(const void* p) {
    uint32_t a;
    asm("{ .reg .u64 t; cvta.to.shared.u64 t, %1; cvt.u32.u64 %0, t; }"
        : "=r"(a) : "l"(p));
    return a;
}
__device__ __forceinline__ void cpa16(uint32_t dst, const void* src) {
    asm volatile("cp.async.cg.shared.global [%0], [%1], 16;"
                 :: "r"(dst), "l"(__cvta_generic_to_global(src)) : "memory");
}
__device__ __forceinline__ void ldsm4(uint32_t* r, uint32_t a) {
    asm volatile("ldmatrix.sync.aligned.m8n8.x4.shared.b16 {%0,%1,%2,%3}, [%4];"
                 : "=r"(r[0]), "=r"(r[1]), "=r"(r[2]), "=r"(r[3]) : "r"(a));
}
__device__ __forceinline__ void mma16816(float* c, const uint32_t* a,
                                         const uint32_t* b) {
    asm volatile(
        "mma.sync.aligned.m16n8k16.row.col.f32.f16.f16.f32 "
        "{%0,%1,%2,%3}, {%4,%5,%6,%7}, {%8,%9}, {%0,%1,%2,%3};"
        : "+f"(c[0]), "+f"(c[1]), "+f"(c[2]), "+f"(c[3])
        : "r"(a[0]), "r"(a[1]), "r"(a[2]), "r"(a[3]), "r"(b[0]), "r"(b[1]));
}

// SMEM stage: A +0 (16KB)  B +16384 (16KB) -> 32KB/stage, 3 stages = 96KB
#define A_OFF 0u
#define B_OFF 16384u
#define STAGE_BYTES 32768u
#define NBUF 3
#define SMEM_BYTES (1024 + NBUF * 32768)

extern __shared__ char dyn_smem[];

__global__ __launch_bounds__(256, 2)
void tdnn_mma(const float* __restrict__ bias, float* __restrict__ out) {
    const int tid  = threadIdx.x;
    const int wid  = tid >> 5;
    const int lane = tid & 31;
    const int d0 = blockIdx.x * TILE_M;
    const int t0 = blockIdx.y * TILE_N;
    const int b  = blockIdx.z;

    const int wm = wid & 1;   // 2 warps along M (64 rows each)
    const int wn = wid >> 1;  // 4 warps along N (32 cols each)

    const uint32_t sb = (smem_u32(dyn_smem) + 1023u) & ~1023u;
    const int rmax = (TIN - KW) - t0;

    // ---- per-lane ldmatrix address precompute (SW128: 128B rows) ----
    const int grp  = lane >> 3;
    const int apar = grp >> 1;           // A: k-chunk parity
    uint32_t a_off[4]; int a_sw[4];
    #pragma unroll
    for (int mt = 0; mt < 4; ++mt) {
        int r = wm * 64 + mt * 16 + ((grp & 1) << 3) + (lane & 7);
        a_off[mt] = (uint32_t)(r << 7);
        a_sw[mt]  = r & 7;
    }
    const int bpar  = grp & 1;           // B: k-chunk parity
    const int ntoff = grp >> 1;
    uint32_t b_off[2]; int b_sw[2];
    #pragma unroll
    for (int np = 0; np < 2; ++np) {
        int r = wn * 32 + np * 16 + ntoff * 8 + (lane & 7);
        b_off[np] = (uint32_t)(r << 7);
        b_sw[np]  = r & 7;
    }

    float acc[4][4][4];
    #pragma unroll
    for (int mt = 0; mt < 4; ++mt)
        #pragma unroll
        for (int nt = 0; nt < 4; ++nt)
            #pragma unroll
            for (int q = 0; q < 4; ++q) acc[mt][nt][q] = 0.0f;

    auto load_stage = [&](int s, uint32_t base) {
        const int kc = s * KC;
        #pragma unroll 4
        for (int c = tid; c < 1024; c += 256) {      // A: 128 rows x 8 chunks
            int row = c >> 3, ch = c & 7;
            uint32_t off = (uint32_t)((row << 7) | ((ch ^ (row & 7)) << 4));
            size_t gi = (size_t)(d0 + row) * KTOT + kc + ch * 8;
            cpa16(base + A_OFF + off, g_wh + gi);
        }
        #pragma unroll 4
        for (int c = tid; c < 1024; c += 256) {      // B: 128 rows x 8 chunks
            int row = c >> 3, ch = c & 7;
            int t = t0 + min(row, rmax);             // clamp; outputs masked
            uint32_t off = (uint32_t)((row << 7) | ((ch ^ (row & 7)) << 4));
            size_t gi = (size_t)b * (TIN * DIN) + (size_t)t * DIN + kc + ch * 8;
            cpa16(base + B_OFF + off, g_xh + gi);
        }
        asm volatile("cp.async.commit_group;" ::: "memory");
    };

    load_stage(0, sb);
    load_stage(1, sb + STAGE_BYTES);

    uint32_t cbuf = 0, lbuf = 2;   // compute buf (s%3), load buf ((s+2)%3)
    for (int s = 0; s < NSTAGE; ++s) {
        if (s < NSTAGE - 1) asm volatile("cp.async.wait_group 1;" ::: "memory");
        else                asm volatile("cp.async.wait_group 0;" ::: "memory");
        __syncthreads();
        // Issue next load FIRST: buffer (s+2)%3 == (s-1)%3, whose compute all
        // warps finished before this barrier.
        if (s + 2 < NSTAGE) load_stage(s + 2, sb + lbuf * STAGE_BYTES);

        const uint32_t base = sb + cbuf * STAGE_BYTES;
        #pragma unroll
        for (int kk = 0; kk < 4; ++kk) {
            uint32_t af[4][4], bf[8];
            #pragma unroll
            for (int mt = 0; mt < 4; ++mt) {
                uint32_t co = (uint32_t)((((kk << 1) + apar) ^ a_sw[mt]) << 4);
                ldsm4(af[mt], base + A_OFF + a_off[mt] + co);
            }
            #pragma unroll
            for (int np = 0; np < 2; ++np) {
                uint32_t co = (uint32_t)((((kk << 1) + bpar) ^ b_sw[np]) << 4);
                ldsm4(&bf[np * 4], base + B_OFF + b_off[np] + co);
            }
            #pragma unroll
            for (int mt = 0; mt < 4; ++mt)
                #pragma unroll
                for (int nt = 0; nt < 4; ++nt)
                    mma16816(acc[mt][nt], af[mt], &bf[nt * 2]);
        }
        cbuf = (cbuf == NBUF - 1) ? 0 : cbuf + 1;
        lbuf = (lbuf == NBUF - 1) ? 0 : lbuf + 1;
    }

    // ---- epilogue: bias + relu; float2 stores ----
    const int quad = lane >> 2;
    const int qt   = (lane & 3) << 1;
    #pragma unroll
    for (int mt = 0; mt < 4; ++mt) {
        const int m = d0 + wm * 64 + mt * 16 + quad;
        const float bv0 = bias[m];
        const float bv1 = bias[m + 8];
        float* r0 = out + ((size_t)b * DOUT + m) * TOUT;
        float* r1 = r0 + 8 * TOUT;
        #pragma unroll
        for (int nt = 0; nt < 4; ++nt) {
            const int t = t0 + wn * 32 + nt * 8 + qt;
            if (t < TOUT) {
                float2 v0, v1;
                v0.x = fmaxf(acc[mt][nt][0] + bv0, 0.0f);
                v0.y = fmaxf(acc[mt][nt][1] + bv0, 0.0f);
                v1.x = fmaxf(acc[mt][nt][2] + bv1, 0.0f);
                v1.y = fmaxf(acc[mt][nt][3] + bv1, 0.0f);
                *(float2*)&r0[t] = v0;
                *(float2*)&r1[t] = v1;
            }
        }
    }
}

extern "C" void kernel_launch(void* const* d_in, const int* in_sizes, int n_in,
                              void* d_out, int out_size) {
    const float* x    = (const float*)d_in[0];
    const float* w    = (const float*)d_in[1];
    const float* bias = (const float*)d_in[2];
    float* out = (float*)d_out;

    cudaFuncSetAttribute(tdnn_mma, cudaFuncAttributeMaxDynamicSharedMemorySize,
                         SMEM_BYTES);

    split_inputs<<<XVEC_BLOCKS + WPAIR_BLOCKS, 256>>>(x, w);

    dim3 grid(DOUT / TILE_M, (TOUT + TILE_N - 1) / TILE_N, BATCH);  // (4,8,32)
    tdnn_mma<<<grid, 256, SMEM_BYTES>>>(bias, out);
}